// round 1
// baseline (speedup 1.0000x reference)
#include <cuda_runtime.h>

// dw[p][q] = LR * ( (1/B) * sum_b post[b][p] * pre[b][q]  -  WD * W[p][q] )
// B=128, POST=1024, PRE=1024.
// GEMM: M=p (post cols), N=q (pre cols), K=b. Both operands are K-major in
// global memory already (row-major [B, 1024]) so SMEM tiles need no transpose.

#define B_DIM   128
#define DIM     1024
#define BM      128   // M tile (post dim)
#define BN      64    // N tile (pre dim)
#define BK      128   // full K
#define TM      8
#define TN      4
#define NTHREADS 256

__global__ __launch_bounds__(NTHREADS, 1)
void hebbian_dw_kernel(const float* __restrict__ pre,
                       const float* __restrict__ post,
                       const float* __restrict__ W,
                       float* __restrict__ out)
{
    extern __shared__ float smem[];
    float* As = smem;               // [BK][BM]  post tile, k-major
    float* Bs = smem + BK * BM;     // [BK][BN]  pre tile,  k-major

    const int tid = threadIdx.x;
    const int pm0 = blockIdx.y * BM;   // post (row of out) base
    const int qn0 = blockIdx.x * BN;   // pre  (col of out) base

    // ---- load tiles (float4, fully coalesced: each warp reads 512B / 256B
    //      contiguous segments per step) ----
    #pragma unroll
    for (int i = tid; i < (BK * BM) / 4; i += NTHREADS) {
        const int k = i >> 5;          // 32 float4 per k-row of As
        const int c = i & 31;
        float4 v = ((const float4*)(post + k * DIM + pm0))[c];
        ((float4*)(As + k * BM))[c] = v;
    }
    #pragma unroll
    for (int i = tid; i < (BK * BN) / 4; i += NTHREADS) {
        const int k = i >> 4;          // 16 float4 per k-row of Bs
        const int c = i & 15;
        float4 v = ((const float4*)(pre + k * DIM + qn0))[c];
        ((float4*)(Bs + k * BN))[c] = v;
    }
    __syncthreads();

    // ---- compute: 16x16 thread grid, each thread owns TM x TN outputs ----
    const int tx = tid & 15;           // n direction
    const int ty = tid >> 4;           // m direction
    const int m0 = ty * TM;
    const int n0 = tx * TN;

    float acc[TM][TN];
    #pragma unroll
    for (int i = 0; i < TM; ++i)
        #pragma unroll
        for (int j = 0; j < TN; ++j)
            acc[i][j] = 0.0f;

    #pragma unroll 8
    for (int k = 0; k < BK; ++k) {
        const float4 a0 = ((const float4*)(As + k * BM + m0))[0];
        const float4 a1 = ((const float4*)(As + k * BM + m0))[1];
        const float4 b  = ((const float4*)(Bs + k * BN + n0))[0];
        const float am[TM] = {a0.x, a0.y, a0.z, a0.w, a1.x, a1.y, a1.z, a1.w};
        const float bn[TN] = {b.x, b.y, b.z, b.w};
        #pragma unroll
        for (int i = 0; i < TM; ++i)
            #pragma unroll
            for (int j = 0; j < TN; ++j)
                acc[i][j] = fmaf(am[i], bn[j], acc[i][j]);
    }

    // ---- fused epilogue: dw = LR * (acc/B - WD * W) ----
    const float invB = 1.0f / (float)B_DIM;
    const float LR = 0.005f;
    const float WD = 0.0001f;

    #pragma unroll
    for (int i = 0; i < TM; ++i) {
        const int row = pm0 + m0 + i;
        const int col = qn0 + n0;
        const float4 w4 = *((const float4*)(W + (size_t)row * DIM + col));
        float4 o;
        o.x = LR * (acc[i][0] * invB - WD * w4.x);
        o.y = LR * (acc[i][1] * invB - WD * w4.y);
        o.z = LR * (acc[i][2] * invB - WD * w4.z);
        o.w = LR * (acc[i][3] * invB - WD * w4.w);
        *((float4*)(out + (size_t)row * DIM + col)) = o;
    }
}

extern "C" void kernel_launch(void* const* d_in, const int* in_sizes, int n_in,
                              void* d_out, int out_size)
{
    const float* pre  = (const float*)d_in[0];   // (128, 1024)
    const float* post = (const float*)d_in[1];   // (128, 1024)
    const float* W    = (const float*)d_in[2];   // (1024, 1024)
    float* out = (float*)d_out;                  // (1024, 1024)

    const int smem_bytes = (BK * BM + BK * BN) * (int)sizeof(float); // 96 KB
    static bool attr_set = false;  // idempotent attribute set (not a stream op)
    if (!attr_set) {
        cudaFuncSetAttribute(hebbian_dw_kernel,
                             cudaFuncAttributeMaxDynamicSharedMemorySize,
                             smem_bytes);
        attr_set = true;
    }

    dim3 grid(DIM / BN, DIM / BM);   // (16, 8) = 128 CTAs
    hebbian_dw_kernel<<<grid, NTHREADS, smem_bytes>>>(pre, post, W, out);
}

// round 3
// speedup vs baseline: 1.2703x; 1.2703x over previous
#include <cuda_runtime.h>
#include <cuda_bf16.h>
#include <cstdint>

// dw[p][q] = LR * ( (1/B)*sum_b post[b][p]*pre[b][q] - WD*W[p][q] )
// B=128, P=Q=1024.  GEMM via legacy mma.sync (sm_80 PTX -> works on compute_103
// base target): D[m=p][n=q] = sum_k A[m][k]*B[n][k], k = b.
// fp32 -> bf16 hi+lo split, 3 accumulating passes => rel err ~1e-5.

#define DIM      1024
#define NTHREADS 256
#define BM       128
#define BN       64
#define BK       128
#define LDA      136            // bf16 elements per SMEM row (272B pitch)

// SMEM byte offsets
#define AH_OFF   0
#define AL_OFF   (BM * LDA * 2)                 // 34816
#define BH_OFF   (2 * BM * LDA * 2)             // 69632
#define BL_OFF   (2 * BM * LDA * 2 + BN * LDA * 2)
#define SMEM_TOTAL (2 * BM * LDA * 2 + 2 * BN * LDA * 2)  // 104448 B

static __device__ __forceinline__ uint32_t smem_u32(const void* p) {
    uint32_t a;
    asm("{ .reg .u64 t; cvta.to.shared.u64 t, %1; cvt.u32.u64 %0, t; }" : "=r"(a) : "l"(p));
    return a;
}

static __device__ __forceinline__ void ldsm_x4(uint32_t* r, uint32_t addr) {
    asm volatile("ldmatrix.sync.aligned.m8n8.x4.shared.b16 {%0,%1,%2,%3}, [%4];"
                 : "=r"(r[0]), "=r"(r[1]), "=r"(r[2]), "=r"(r[3]) : "r"(addr));
}

static __device__ __forceinline__ void mma16816(float* c, const uint32_t* a,
                                                uint32_t b0, uint32_t b1) {
    asm volatile(
        "mma.sync.aligned.m16n8k16.row.col.f32.bf16.bf16.f32 "
        "{%0,%1,%2,%3}, {%4,%5,%6,%7}, {%8,%9}, {%0,%1,%2,%3};"
        : "+f"(c[0]), "+f"(c[1]), "+f"(c[2]), "+f"(c[3])
        : "r"(a[0]), "r"(a[1]), "r"(a[2]), "r"(a[3]), "r"(b0), "r"(b1));
}

// Convert a (rows x 128) fp32 slab (gmem [k][col0+row], row contiguous) into
// bf16 hi/lo SMEM tiles laid out [row][k] (k contiguous), LDA pitch.
// Each unit: one row, 8 consecutive k. LDG.32 coalesced over rows; STS.128
// conflict-free (272B pitch covers all 32 banks per 8-lane phase).
template <int ROWS>
static __device__ __forceinline__ void convert_tile(const float* __restrict__ src, int col0,
                                                    char* sm_hi, char* sm_lo, int tid) {
    #pragma unroll
    for (int it = 0; it < ROWS * 16 / NTHREADS; ++it) {
        const int u  = tid + NTHREADS * it;
        const int m  = u & (ROWS - 1);
        const int k0 = (u / ROWS) * 8;
        const float* p = src + (size_t)k0 * DIM + col0 + m;
        uint32_t hi[8], lo[8];
        #pragma unroll
        for (int j = 0; j < 8; ++j) {
            const float v = p[(size_t)j * DIM];
            const __nv_bfloat16 h = __float2bfloat16_rn(v);
            hi[j] = (uint32_t)__bfloat16_as_ushort(h);
            lo[j] = (uint32_t)__bfloat16_as_ushort(
                        __float2bfloat16_rn(v - __bfloat162float(h)));
        }
        uint4 hv, lv;
        hv.x = hi[0] | (hi[1] << 16); hv.y = hi[2] | (hi[3] << 16);
        hv.z = hi[4] | (hi[5] << 16); hv.w = hi[6] | (hi[7] << 16);
        lv.x = lo[0] | (lo[1] << 16); lv.y = lo[2] | (lo[3] << 16);
        lv.z = lo[4] | (lo[5] << 16); lv.w = lo[6] | (lo[7] << 16);
        const int off = (m * LDA + k0) * 2;
        *(uint4*)(sm_hi + off) = hv;
        *(uint4*)(sm_lo + off) = lv;
    }
}

__global__ __launch_bounds__(NTHREADS, 1)
void hebbian_mma_kernel(const float* __restrict__ pre,
                        const float* __restrict__ post,
                        const float* __restrict__ W,
                        float* __restrict__ out)
{
    extern __shared__ char smem[];
    const int tid  = threadIdx.x;
    const int lane = tid & 31;
    const int wid  = tid >> 5;
    const int pm0  = blockIdx.y * BM;   // output row (post) base
    const int qn0  = blockIdx.x * BN;   // output col (pre)  base

    // ---- convert operands: fp32 -> bf16 hi/lo, transposed into k-major SMEM ----
    convert_tile<BM>(post, pm0, smem + AH_OFF, smem + AL_OFF, tid);
    convert_tile<BN>(pre,  qn0, smem + BH_OFF, smem + BL_OFF, tid);
    __syncthreads();

    // ---- mma mainloop: warp grid 4(m) x 2(n), warp tile 32x32 ----
    const int wm = (wid >> 1) * 32;
    const int wn = (wid & 1) * 32;
    const uint32_t sbase = smem_u32(smem);

    float acc[2][4][4];
    #pragma unroll
    for (int i = 0; i < 2; ++i)
        #pragma unroll
        for (int j = 0; j < 4; ++j)
            #pragma unroll
            for (int r = 0; r < 4; ++r)
                acc[i][j][r] = 0.0f;

    const int frow = lane & 15;          // fragment row within 16-block
    const int fcol = (lane >> 4) * 8;    // k half (0 or 8)

    #pragma unroll
    for (int ks = 0; ks < BK / 16; ++ks) {
        const int kb = ks * 16 + fcol;
        uint32_t ah[2][4], al[2][4], bh[2][4], bl[2][4];
        #pragma unroll
        for (int mi = 0; mi < 2; ++mi) {
            const uint32_t off = ((wm + mi * 16 + frow) * LDA + kb) * 2;
            ldsm_x4(ah[mi], sbase + AH_OFF + off);
            ldsm_x4(al[mi], sbase + AL_OFF + off);
        }
        #pragma unroll
        for (int nb = 0; nb < 2; ++nb) {
            const uint32_t off = ((wn + nb * 16 + frow) * LDA + kb) * 2;
            ldsm_x4(bh[nb], sbase + BH_OFF + off);
            ldsm_x4(bl[nb], sbase + BL_OFF + off);
        }
        #pragma unroll
        for (int mi = 0; mi < 2; ++mi)
            #pragma unroll
            for (int nn = 0; nn < 4; ++nn) {
                const int nb = nn >> 1, sel = nn & 1;
                mma16816(acc[mi][nn], ah[mi], bh[nb][sel], bh[nb][sel + 2]);  // hi*hi
                mma16816(acc[mi][nn], ah[mi], bl[nb][sel], bl[nb][sel + 2]);  // hi*lo
                mma16816(acc[mi][nn], al[mi], bh[nb][sel], bh[nb][sel + 2]);  // lo*hi
            }
    }

    // ---- fused epilogue: dw = acc*(LR/B) - (LR*WD)*W ----
    const float c1 = 0.005f / 128.0f;
    const float c2 = 0.005f * 0.0001f;
    const int qcol = qn0 + wn + (lane & 3) * 2;
    const int prow = pm0 + wm + (lane >> 2);

    #pragma unroll
    for (int mi = 0; mi < 2; ++mi)
        #pragma unroll
        for (int nn = 0; nn < 4; ++nn) {
            const int q = qcol + nn * 8;
            #pragma unroll
            for (int h = 0; h < 2; ++h) {           // h=0: rows t/4, h=1: +8
                const int p = prow + mi * 16 + h * 8;
                const float2 w2 = *(const float2*)(W + (size_t)p * DIM + q);
                float2 o;
                o.x = fmaf(acc[mi][nn][2 * h + 0], c1, -c2 * w2.x);
                o.y = fmaf(acc[mi][nn][2 * h + 1], c1, -c2 * w2.y);
                *(float2*)(out + (size_t)p * DIM + q) = o;
            }
        }
}

extern "C" void kernel_launch(void* const* d_in, const int* in_sizes, int n_in,
                              void* d_out, int out_size)
{
    const float* pre  = (const float*)d_in[0];   // (128, 1024)
    const float* post = (const float*)d_in[1];   // (128, 1024)
    const float* W    = (const float*)d_in[2];   // (1024, 1024)
    float* out = (float*)d_out;                  // (1024, 1024)

    static bool attr_set = false;
    if (!attr_set) {
        cudaFuncSetAttribute(hebbian_mma_kernel,
                             cudaFuncAttributeMaxDynamicSharedMemorySize, SMEM_TOTAL);
        attr_set = true;
    }
    dim3 grid(DIM / BN, DIM / BM);   // (16, 8) = 128 CTAs
    hebbian_mma_kernel<<<grid, NTHREADS, SMEM_TOTAL>>>(pre, post, W, out);
}

// round 4
// speedup vs baseline: 1.2741x; 1.0029x over previous
#include <cuda_runtime.h>
#include <cuda_bf16.h>
#include <cstdint>

// dw[p][q] = LR * ( (1/B)*sum_b post[b][p]*pre[b][q] - WD*W[p][q] )
// B=128, P=Q=1024.  Legacy mma.sync bf16 (base compute_103 PTX), fp32 hi/lo
// split, 3 accumulating passes. 64x64 CTA tile, 2 CTAs/SM, W prefetched into
// registers across the MMA mainloop.

#define DIM      1024
#define NTHREADS 256
#define BM       64
#define BN       64
#define BK       128
#define LDA      136                       // bf16/row pitch (272B): STS.128 + ldmatrix conflict-free

#define TILE_B   (BM * LDA * 2)            // 17408
#define AH_OFF   0
#define AL_OFF   TILE_B
#define BH_OFF   (2 * TILE_B)
#define BL_OFF   (3 * TILE_B)
#define SMEM_TOTAL (4 * TILE_B)            // 69632 B -> 2 CTAs/SM

static __device__ __forceinline__ uint32_t smem_u32(const void* p) {
    uint32_t a;
    asm("{ .reg .u64 t; cvta.to.shared.u64 t, %1; cvt.u32.u64 %0, t; }" : "=r"(a) : "l"(p));
    return a;
}
static __device__ __forceinline__ void ldsm_x4(uint32_t* r, uint32_t addr) {
    asm volatile("ldmatrix.sync.aligned.m8n8.x4.shared.b16 {%0,%1,%2,%3}, [%4];"
                 : "=r"(r[0]), "=r"(r[1]), "=r"(r[2]), "=r"(r[3]) : "r"(addr));
}
static __device__ __forceinline__ void mma16816(float* c, const uint32_t* a,
                                                uint32_t b0, uint32_t b1) {
    asm volatile(
        "mma.sync.aligned.m16n8k16.row.col.f32.bf16.bf16.f32 "
        "{%0,%1,%2,%3}, {%4,%5,%6,%7}, {%8,%9}, {%0,%1,%2,%3};"
        : "+f"(c[0]), "+f"(c[1]), "+f"(c[2]), "+f"(c[3])
        : "r"(a[0]), "r"(a[1]), "r"(a[2]), "r"(a[3]), "r"(b0), "r"(b1));
}

// fp32 (gmem [k][col0+row], row contiguous) -> bf16 hi/lo SMEM [row][k].
// 64 rows x 128 k = 1024 units of 8 k; 4 iters per 256 threads.
static __device__ __forceinline__ void convert_tile(const float* __restrict__ src, int col0,
                                                    char* sm_hi, char* sm_lo, int tid) {
    #pragma unroll
    for (int it = 0; it < 4; ++it) {
        const int u  = tid + NTHREADS * it;
        const int m  = u & 63;
        const int k0 = (u >> 6) * 8;
        const float* p = src + (size_t)k0 * DIM + col0 + m;
        uint32_t hi[8], lo[8];
        #pragma unroll
        for (int j = 0; j < 8; ++j) {
            const float v = p[(size_t)j * DIM];
            const __nv_bfloat16 h = __float2bfloat16_rn(v);
            hi[j] = (uint32_t)__bfloat16_as_ushort(h);
            lo[j] = (uint32_t)__bfloat16_as_ushort(
                        __float2bfloat16_rn(v - __bfloat162float(h)));
        }
        uint4 hv, lv;
        hv.x = hi[0] | (hi[1] << 16); hv.y = hi[2] | (hi[3] << 16);
        hv.z = hi[4] | (hi[5] << 16); hv.w = hi[6] | (hi[7] << 16);
        lv.x = lo[0] | (lo[1] << 16); lv.y = lo[2] | (lo[3] << 16);
        lv.z = lo[4] | (lo[5] << 16); lv.w = lo[6] | (lo[7] << 16);
        const int off = (m * LDA + k0) * 2;
        *(uint4*)(sm_hi + off) = hv;
        *(uint4*)(sm_lo + off) = lv;
    }
}

__global__ __launch_bounds__(NTHREADS, 2)
void hebbian_mma_kernel(const float* __restrict__ pre,
                        const float* __restrict__ post,
                        const float* __restrict__ W,
                        float* __restrict__ out)
{
    extern __shared__ char smem[];
    const int tid  = threadIdx.x;
    const int lane = tid & 31;
    const int wid  = tid >> 5;
    const int pm0  = blockIdx.y * BM;   // output row (post) base
    const int qn0  = blockIdx.x * BN;   // output col (pre)  base

    // ---- convert operands into SMEM (bf16 hi/lo, k-major) ----
    convert_tile(post, pm0, smem + AH_OFF, smem + AL_OFF, tid);
    convert_tile(pre,  qn0, smem + BH_OFF, smem + BL_OFF, tid);

    // ---- warp tiling: 4(m) x 2(n) warps, warp tile m16 x n32 ----
    const int wm = (wid >> 1) * 16;
    const int wn = (wid & 1) * 32;

    // ---- prefetch W for this thread's outputs (hides DRAM behind MMA) ----
    const int prow = pm0 + wm + (lane >> 2);
    const int qcol = qn0 + wn + (lane & 3) * 2;
    float2 wv[4][2];
    #pragma unroll
    for (int nn = 0; nn < 4; ++nn) {
        const int q = qcol + nn * 8;
        wv[nn][0] = *(const float2*)(W + (size_t)prow * DIM + q);
        wv[nn][1] = *(const float2*)(W + (size_t)(prow + 8) * DIM + q);
    }

    __syncthreads();

    const uint32_t sbase = smem_u32(smem);
    float acc[4][4];
    #pragma unroll
    for (int j = 0; j < 4; ++j)
        #pragma unroll
        for (int r = 0; r < 4; ++r)
            acc[j][r] = 0.0f;

    const int frow = lane & 15;          // row within 16-block
    const int fcol = (lane >> 4) * 8;    // k half (0 or 8)

    #pragma unroll
    for (int ks = 0; ks < BK / 16; ++ks) {
        const int kb = ks * 16 + fcol;
        uint32_t ah[4], al[4], bh[2][4], bl[2][4];
        {
            const uint32_t off = ((wm + frow) * LDA + kb) * 2;
            ldsm_x4(ah, sbase + AH_OFF + off);
            ldsm_x4(al, sbase + AL_OFF + off);
        }
        #pragma unroll
        for (int nb = 0; nb < 2; ++nb) {
            const uint32_t off = ((wn + nb * 16 + frow) * LDA + kb) * 2;
            ldsm_x4(bh[nb], sbase + BH_OFF + off);
            ldsm_x4(bl[nb], sbase + BL_OFF + off);
        }
        #pragma unroll
        for (int nn = 0; nn < 4; ++nn) {
            const int nb = nn >> 1, sel = nn & 1;
            mma16816(acc[nn], ah, bh[nb][sel], bh[nb][sel + 2]);  // hi*hi
            mma16816(acc[nn], ah, bl[nb][sel], bl[nb][sel + 2]);  // hi*lo
            mma16816(acc[nn], al, bh[nb][sel], bh[nb][sel + 2]);  // lo*hi
        }
    }

    // ---- fused epilogue: dw = acc*(LR/B) - (LR*WD)*W (W already in regs) ----
    const float c1 = 0.005f / 128.0f;
    const float c2 = 0.005f * 0.0001f;
    #pragma unroll
    for (int nn = 0; nn < 4; ++nn) {
        const int q = qcol + nn * 8;
        #pragma unroll
        for (int h = 0; h < 2; ++h) {
            const int p = prow + h * 8;
            float2 o;
            o.x = fmaf(acc[nn][2 * h + 0], c1, -c2 * wv[nn][h].x);
            o.y = fmaf(acc[nn][2 * h + 1], c1, -c2 * wv[nn][h].y);
            *(float2*)(out + (size_t)p * DIM + q) = o;
        }
    }
}

extern "C" void kernel_launch(void* const* d_in, const int* in_sizes, int n_in,
                              void* d_out, int out_size)
{
    const float* pre  = (const float*)d_in[0];   // (128, 1024)
    const float* post = (const float*)d_in[1];   // (128, 1024)
    const float* W    = (const float*)d_in[2];   // (1024, 1024)
    float* out = (float*)d_out;                  // (1024, 1024)

    static bool attr_set = false;
    if (!attr_set) {
        cudaFuncSetAttribute(hebbian_mma_kernel,
                             cudaFuncAttributeMaxDynamicSharedMemorySize, SMEM_TOTAL);
        attr_set = true;
    }
    dim3 grid(DIM / BN, DIM / BM);   // (16, 16) = 256 CTAs
    hebbian_mma_kernel<<<grid, NTHREADS, SMEM_TOTAL>>>(pre, post, W, out);
}